// round 6
// baseline (speedup 1.0000x reference)
#include <cuda_runtime.h>
#include <cuda_fp16.h>
#include <math.h>

#define BATCH 64
#define CH 3
#define NIMG (BATCH*CH)     /* 192 */
#define IMH 256
#define IMW 256
#define NB 256
#define NPIX (CH*IMH*IMW)   /* 196608 per batch */
#define RAD 5
#define KS 11

typedef unsigned long long ull;

// packed f32x2 helpers (ptxas never emits FFMA2 from C++; PTX-only path)
#define F32X2_FMA(d, a, b, c) \
    asm("fma.rn.f32x2 %0, %1, %2, %3;" : "=l"(d) : "l"(a), "l"(b), "l"(c))
#define F32X2_MUL(d, a, b) \
    asm("mul.rn.f32x2 %0, %1, %2;" : "=l"(d) : "l"(a), "l"(b))
#define F32X2_PACK(d, lo, hi) \
    asm("mov.b64 %0, {%1, %2};" : "=l"(d) : "f"(lo), "f"(hi))
#define F32X2_UNPACK(lo, hi, d) \
    asm("mov.b64 {%0, %1}, %2;" : "=f"(lo), "=f"(hi) : "l"(d))

// Scratch (device globals: allocation-free per harness rules)
__device__ unsigned int d_hist[BATCH * NB * NB];        // 16 MB joint histograms
__device__ unsigned int d_py[BATCH * NB];               // marginal-y partial sums
__device__ double d_hx[BATCH];
__device__ double d_hxy[BATCH];
__device__ double d_ssim_sum[BATCH];
__device__ double d_mse_sum[BATCH];
// fp16-staged horizontally-convolved fields (125 MB total)
__device__ __half2 d_f01[NIMG * IMH * IMW];             // (conv x, conv y)
__device__ __half2 d_f23[NIMG * IMH * IMW];             // (conv x2, conv y2)
__device__ __half  d_f4 [NIMG * IMH * IMW];             // conv xy

// ---------------------------------------------------------------------------
// Kernel 1: zero scratch (vectorized)
// ---------------------------------------------------------------------------
__global__ void bsm_zero_kernel() {
    int idx = blockIdx.x * blockDim.x + threadIdx.x;
    int stride = gridDim.x * blockDim.x;
    uint4* p = (uint4*)d_hist;
    const int total4 = (BATCH * NB * NB) / 4;
    for (int i = idx; i < total4; i += stride)
        p[i] = make_uint4(0u, 0u, 0u, 0u);
    if (idx < BATCH * NB) d_py[idx] = 0u;
    if (idx < BATCH) {
        d_hx[idx] = 0.0;
        d_hxy[idx] = 0.0;
        d_ssim_sum[idx] = 0.0;
        d_mse_sum[idx]  = 0.0;
    }
}

// ---------------------------------------------------------------------------
// Kernel 2 (K_H): horizontal 11-tap pass over full rows + MI hist + MSE.
// block = 256 threads handles 4 rows of one image. grid = (IMH/4, NIMG).
// Packed f32x2 accumulation: (conv_x,conv_y) and (conv_x2,conv_y2).
// ---------------------------------------------------------------------------
__global__ __launch_bounds__(256) void bsm_h_kernel(
    const float* __restrict__ x,
    const float* __restrict__ y,
    const float* __restrict__ win)
{
    const int tid = threadIdx.x;
    const int img = blockIdx.y;
    const int b   = img / CH;
    const int r0  = blockIdx.x * 4;

    __shared__ float2 sxy[4][268];     // interleaved (x,y)
    __shared__ float g1[16];
    __shared__ double sred[8];

    // Separable 1D gaussian = row sums of the 2D window (sum(g)=1).
    if (tid < KS) {
        float s = 0.f;
        #pragma unroll
        for (int j = 0; j < KS; j++) s += win[tid * KS + j];
        g1[tid] = s;
    }
    // zero halos (image edge -> zero pad)
    if (tid < 5) {
        #pragma unroll
        for (int j = 0; j < 4; j++) {
            sxy[j][tid] = make_float2(0.f, 0.f);
            sxy[j][IMW + 5 + tid] = make_float2(0.f, 0.f);
        }
    }

    const size_t ibase = (size_t)img * (IMH * IMW);
    float mse_loc = 0.f;

    #pragma unroll
    for (int j = 0; j < 4; j++) {
        size_t base = ibase + (size_t)(r0 + j) * IMW;
        float xv = x[base + tid];
        float yv = y[base + tid];
        sxy[j][5 + tid] = make_float2(xv, yv);

        // MI binning (exact reference op order) + MSE
        float xf = (xv + 1.0f) * 0.5f;
        float yf = (yv + 1.0f) * 0.5f;
        int ix = (int)(xf * 256.0f); ix = min(max(ix, 0), NB - 1);
        int iy = (int)(yf * 256.0f); iy = min(max(iy, 0), NB - 1);
        atomicAdd(&d_hist[b * (NB * NB) + ix * NB + iy], 1u);
        float d = (xv * 0.5f + 0.5f) - (yv * 0.5f + 0.5f);
        mse_loc = fmaf(d, d, mse_loc);
    }
    __syncthreads();

    // packed (w,w) weights
    ull ww[KS];
    #pragma unroll
    for (int k = 0; k < KS; k++) { float w = g1[k]; F32X2_PACK(ww[k], w, w); }

    #pragma unroll
    for (int j = 0; j < 4; j++) {
        ull a01 = 0ull, a23 = 0ull;
        float a4 = 0.f;
        #pragma unroll
        for (int k = 0; k < KS; k++) {
            float2 v = sxy[j][tid + k];
            ull vp; F32X2_PACK(vp, v.x, v.y);
            F32X2_FMA(a01, ww[k], vp, a01);
            ull sq; F32X2_MUL(sq, vp, vp);
            F32X2_FMA(a23, ww[k], sq, a23);
            a4 = fmaf(g1[k], v.x * v.y, a4);
        }
        float a0, a1, a2, a3;
        F32X2_UNPACK(a0, a1, a01);
        F32X2_UNPACK(a2, a3, a23);
        size_t o = ibase + (size_t)(r0 + j) * IMW + tid;
        d_f01[o] = __floats2half2_rn(a0, a1);
        d_f23[o] = __floats2half2_rn(a2, a3);
        d_f4[o]  = __float2half_rn(a4);
    }

    // block reduce mse -> one double atomic
    #pragma unroll
    for (int off = 16; off; off >>= 1)
        mse_loc += __shfl_down_sync(0xffffffffu, mse_loc, off);
    int lane = tid & 31, warp = tid >> 5;
    if (lane == 0) sred[warp] = (double)mse_loc;
    __syncthreads();
    if (tid == 0) {
        double m = 0.0;
        #pragma unroll
        for (int w = 0; w < 8; w++) m += sred[w];
        atomicAdd(&d_mse_sum[b], m);
    }
}

// ---------------------------------------------------------------------------
// Kernel 3 (K_V): vertical 11-tap pass + SSIM formula + reduction.
// block = 256 threads = 32 cols x 8 row-groups; each row-group -> 4 rows.
// grid = (IMW/32, IMH/32, NIMG). Packed f32x2 accumulation.
// ---------------------------------------------------------------------------
__global__ __launch_bounds__(256) void bsm_v_kernel(const float* __restrict__ win)
{
    const int tid = threadIdx.x;
    const int img = blockIdx.z;
    const int b   = img / CH;

    __shared__ float g1[16];
    __shared__ double sred[8];

    if (tid < KS) {
        float s = 0.f;
        #pragma unroll
        for (int j = 0; j < KS; j++) s += win[tid * KS + j];
        g1[tid] = s;
    }
    __syncthreads();

    ull ww[KS];
    #pragma unroll
    for (int k = 0; k < KS; k++) { float w = g1[k]; F32X2_PACK(ww[k], w, w); }

    const int c   = tid & 31;
    const int col = blockIdx.x * 32 + c;
    const int r0  = blockIdx.y * 32 + (tid >> 5) * 4;
    const size_t ibase = (size_t)img * (IMH * IMW);

    float mu1[4], mu2[4], m11[4], m22[4], m12[4];

    // fields 0,1 (mu1, mu2) — packed
    {
        ull vp[14];
        #pragma unroll
        for (int t = 0; t < 14; t++) {
            int rr = r0 + t - RAD;
            float2 v = (rr >= 0 && rr < IMH)
                 ? __half22float2(d_f01[ibase + (size_t)rr * IMW + col])
                 : make_float2(0.f, 0.f);
            F32X2_PACK(vp[t], v.x, v.y);
        }
        ull acc[4] = {0ull, 0ull, 0ull, 0ull};
        #pragma unroll
        for (int k = 0; k < KS; k++)
            #pragma unroll
            for (int j = 0; j < 4; j++)
                F32X2_FMA(acc[j], ww[k], vp[j + k], acc[j]);
        #pragma unroll
        for (int j = 0; j < 4; j++) F32X2_UNPACK(mu1[j], mu2[j], acc[j]);
    }
    // fields 2,3 (m11, m22) — packed
    {
        ull vp[14];
        #pragma unroll
        for (int t = 0; t < 14; t++) {
            int rr = r0 + t - RAD;
            float2 v = (rr >= 0 && rr < IMH)
                 ? __half22float2(d_f23[ibase + (size_t)rr * IMW + col])
                 : make_float2(0.f, 0.f);
            F32X2_PACK(vp[t], v.x, v.y);
        }
        ull acc[4] = {0ull, 0ull, 0ull, 0ull};
        #pragma unroll
        for (int k = 0; k < KS; k++)
            #pragma unroll
            for (int j = 0; j < 4; j++)
                F32X2_FMA(acc[j], ww[k], vp[j + k], acc[j]);
        #pragma unroll
        for (int j = 0; j < 4; j++) F32X2_UNPACK(m11[j], m22[j], acc[j]);
    }
    // field 4 (m12) — packed across adjacent output rows
    {
        float v[14];
        #pragma unroll
        for (int t = 0; t < 14; t++) {
            int rr = r0 + t - RAD;
            v[t] = (rr >= 0 && rr < IMH)
                 ? __half2float(d_f4[ibase + (size_t)rr * IMW + col]) : 0.f;
        }
        ull p[13];
        #pragma unroll
        for (int t = 0; t < 13; t++) F32X2_PACK(p[t], v[t], v[t + 1]);
        ull acc0 = 0ull, acc1 = 0ull;   // (j0,j1) and (j2,j3)
        #pragma unroll
        for (int k = 0; k < KS; k++) {
            F32X2_FMA(acc0, ww[k], p[k],     acc0);
            F32X2_FMA(acc1, ww[k], p[k + 2], acc1);
        }
        F32X2_UNPACK(m12[0], m12[1], acc0);
        F32X2_UNPACK(m12[2], m12[3], acc1);
    }

    const float C1c = 0.01f * 0.01f;
    const float C2c = 0.03f * 0.03f;
    float ssim_loc = 0.f;
    #pragma unroll
    for (int j = 0; j < 4; j++) {
        float mu1s = mu1[j] * mu1[j];
        float mu2s = mu2[j] * mu2[j];
        float mu12 = mu1[j] * mu2[j];
        float s1  = m11[j] - mu1s;
        float s2  = m22[j] - mu2s;
        float s12 = m12[j] - mu12;
        float num = (2.f * mu12 + C1c) * (2.f * s12 + C2c);
        float den = (mu1s + mu2s + C1c) * (s1 + s2 + C2c);
        ssim_loc += num / den;
    }

    #pragma unroll
    for (int off = 16; off; off >>= 1)
        ssim_loc += __shfl_down_sync(0xffffffffu, ssim_loc, off);
    int lane = tid & 31, warp = tid >> 5;
    if (lane == 0) sred[warp] = (double)ssim_loc;
    __syncthreads();
    if (tid == 0) {
        double s = 0.0;
        #pragma unroll
        for (int w = 0; w < 8; w++) s += sred[w];
        atomicAdd(&d_ssim_sum[b], s);
    }
}

// ---------------------------------------------------------------------------
// Kernel 4a: histogram scan — coalesced uint4 reads.
// grid = (8 chunks, 64 batches), block = 256 (8 warps, warp -> 4 rows).
// ---------------------------------------------------------------------------
__global__ __launch_bounds__(256) void bsm_fin_a_kernel()
{
    const int b     = blockIdx.y;
    const int chunk = blockIdx.x;
    const int tid   = threadIdx.x;
    const int lane  = tid & 31;
    const int warp  = tid >> 5;

    __shared__ unsigned int spy[NB];
    __shared__ double sredA[8], sredB[8];

    spy[tid] = 0u;
    __syncthreads();

    const uint4* hb4 = (const uint4*)&d_hist[b * NB * NB];
    const float invNf = 1.0f / (float)NPIX;

    double hxy_loc = 0.0;
    double hx_loc  = 0.0;

    // warp handles 4 consecutive rows
    #pragma unroll
    for (int rr = 0; rr < 4; rr++) {
        int row = chunk * 32 + warp * 4 + rr;
        uint4 q0 = hb4[row * 64 + lane];
        uint4 q1 = hb4[row * 64 + 32 + lane];
        unsigned int cs[8] = {q0.x, q0.y, q0.z, q0.w, q1.x, q1.y, q1.z, q1.w};

        unsigned int px_part = 0;
        float h_part = 0.f;      // Σ -p*log2(p) over this lane's 8 bins
        #pragma unroll
        for (int k = 0; k < 8; k++) {
            unsigned int cnt = cs[k];
            px_part += cnt;
            if (cnt) {
                float p = (float)cnt * invNf;
                h_part -= p * log2f(p);
                int colk = (k < 4) ? (lane * 4 + k) : (128 + lane * 4 + (k - 4));
                atomicAdd(&spy[colk], cnt);
            }
        }
        hxy_loc += (double)h_part;

        #pragma unroll
        for (int off = 16; off; off >>= 1)
            px_part += __shfl_down_sync(0xffffffffu, px_part, off);
        if (lane == 0 && px_part) {
            float pxn = (float)px_part * invNf;
            hx_loc -= (double)(pxn * log2f(pxn));
        }
    }

    #pragma unroll
    for (int off = 16; off; off >>= 1)
        hxy_loc += __shfl_down_sync(0xffffffffu, hxy_loc, off);
    if (lane == 0) { sredA[warp] = hxy_loc; sredB[warp] = hx_loc; }
    __syncthreads();
    if (tid == 0) {
        double a = 0.0, bb = 0.0;
        #pragma unroll
        for (int w = 0; w < 8; w++) { a += sredA[w]; bb += sredB[w]; }
        atomicAdd(&d_hxy[b], a);
        atomicAdd(&d_hx[b],  bb);
    }
    __syncthreads();
    if (spy[tid]) atomicAdd(&d_py[b * NB + tid], spy[tid]);
}

// ---------------------------------------------------------------------------
// Kernel 4b: combine — H(Y) from d_py, final MI/SSIM/PSNR, write out.
// ---------------------------------------------------------------------------
__global__ __launch_bounds__(256) void bsm_fin_b_kernel(float* __restrict__ out)
{
    const int b = blockIdx.x;
    const int t = threadIdx.x;
    const float invNf = 1.0f / (float)NPIX;
    const double invN = 1.0 / (double)NPIX;

    __shared__ double shy[256];
    unsigned int py = d_py[b * NB + t];
    float pyn = (float)py * invNf;
    shy[t] = (py > 0) ? (double)(-pyn * log2f(pyn)) : 0.0;
    __syncthreads();
    for (int s = 128; s; s >>= 1) {
        if (t < s) shy[t] += shy[t + s];
        __syncthreads();
    }

    if (t == 0) {
        double hx = d_hx[b], hy = shy[0], hxyv = d_hxy[b];
        double mi = hx + hy - hxyv;
        double norm = fmin(hx, hy);
        mi = (norm > 0.0) ? (mi / norm) : 0.0;
        mi = fmin(fmax(mi, 0.0), 1.0);

        double ssim = d_ssim_sum[b] * invN;

        double mse = d_mse_sum[b] * invN;
        double psnr = (mse == 0.0) ? 100.0 : (-10.0 * log10(mse));
        psnr /= 40.0;

        out[b * 3 + 0] = (float)mi;
        out[b * 3 + 1] = (float)ssim;
        out[b * 3 + 2] = (float)psnr;
    }
}

// ---------------------------------------------------------------------------
extern "C" void kernel_launch(void* const* d_in, const int* in_sizes, int n_in,
                              void* d_out, int out_size)
{
    const float* x   = (const float*)d_in[0];
    const float* y   = (const float*)d_in[1];
    const float* win = (const float*)d_in[2];
    float* out = (float*)d_out;

    bsm_zero_kernel<<<2048, 256>>>();

    dim3 gh(IMH / 4, NIMG);
    bsm_h_kernel<<<gh, 256>>>(x, y, win);

    dim3 gv(IMW / 32, IMH / 32, NIMG);
    bsm_v_kernel<<<gv, 256>>>(win);

    dim3 gf(8, BATCH);
    bsm_fin_a_kernel<<<gf, 256>>>();
    bsm_fin_b_kernel<<<BATCH, 256>>>(out);
}

// round 7
// speedup vs baseline: 1.0095x; 1.0095x over previous
#include <cuda_runtime.h>
#include <cuda_fp16.h>
#include <math.h>

#define BATCH 64
#define CH 3
#define NIMG (BATCH*CH)     /* 192 */
#define IMH 256
#define IMW 256
#define NB 256
#define NPIX (CH*IMH*IMW)   /* 196608 per batch */
#define RAD 5
#define KS 11

// Scratch (device globals: zero-initialized at module load; every launch
// leaves them zeroed again => allocation-free AND no zeroing kernel needed)
__device__ unsigned int d_hist[BATCH * NB * NB];        // 16 MB joint histograms
__device__ unsigned int d_py[BATCH * NB];               // marginal-y partial sums
__device__ double d_hx[BATCH];
__device__ double d_hxy[BATCH];
__device__ double d_ssim_sum[BATCH];
__device__ double d_mse_sum[BATCH];
// fp16-staged horizontally-convolved fields (125 MB total)
__device__ __half2 d_f01[NIMG * IMH * IMW];             // (conv x, conv y)
__device__ __half2 d_f23[NIMG * IMH * IMW];             // (conv x2, conv y2)
__device__ __half  d_f4 [NIMG * IMH * IMW];             // conv xy

// ---------------------------------------------------------------------------
// Kernel 1 (K_H): horizontal 11-tap pass over full rows + MI hist + MSE.
// block = 256 threads handles 4 rows of one image. grid = (IMH/4, NIMG).
// Products (x2,y2,xy) hoisted: computed once per pixel, convolved from shared.
// ---------------------------------------------------------------------------
__global__ __launch_bounds__(256) void bsm_h_kernel(
    const float* __restrict__ x,
    const float* __restrict__ y,
    const float* __restrict__ win)
{
    const int tid = threadIdx.x;
    const int img = blockIdx.y;
    const int b   = img / CH;
    const int r0  = blockIdx.x * 4;

    __shared__ float2 sv[4][268];      // (x, y)
    __shared__ float2 sq[4][268];      // (x*x, y*y)
    __shared__ float  sp[4][268];      // x*y
    __shared__ float g1[16];
    __shared__ double sred[8];

    // Separable 1D gaussian = row sums of the 2D window (sum(g)=1).
    if (tid < KS) {
        float s = 0.f;
        #pragma unroll
        for (int j = 0; j < KS; j++) s += win[tid * KS + j];
        g1[tid] = s;
    }
    // zero halos (image edge -> zero pad)
    if (tid < 5) {
        #pragma unroll
        for (int j = 0; j < 4; j++) {
            sv[j][tid] = make_float2(0.f, 0.f);
            sq[j][tid] = make_float2(0.f, 0.f);
            sp[j][tid] = 0.f;
            sv[j][IMW + 5 + tid] = make_float2(0.f, 0.f);
            sq[j][IMW + 5 + tid] = make_float2(0.f, 0.f);
            sp[j][IMW + 5 + tid] = 0.f;
        }
    }

    const size_t ibase = (size_t)img * (IMH * IMW);
    float mse_loc = 0.f;

    #pragma unroll
    for (int j = 0; j < 4; j++) {
        size_t base = ibase + (size_t)(r0 + j) * IMW;
        float xv = x[base + tid];
        float yv = y[base + tid];
        sv[j][5 + tid] = make_float2(xv, yv);
        sq[j][5 + tid] = make_float2(xv * xv, yv * yv);
        sp[j][5 + tid] = xv * yv;

        // MI binning (exact reference op order) + MSE
        float xf = (xv + 1.0f) * 0.5f;
        float yf = (yv + 1.0f) * 0.5f;
        int ix = (int)(xf * 256.0f); ix = min(max(ix, 0), NB - 1);
        int iy = (int)(yf * 256.0f); iy = min(max(iy, 0), NB - 1);
        atomicAdd(&d_hist[b * (NB * NB) + ix * NB + iy], 1u);
        float d = (xv * 0.5f + 0.5f) - (yv * 0.5f + 0.5f);
        mse_loc = fmaf(d, d, mse_loc);
    }
    __syncthreads();

    #pragma unroll
    for (int j = 0; j < 4; j++) {
        float a0 = 0.f, a1 = 0.f, a2 = 0.f, a3 = 0.f, a4 = 0.f;
        #pragma unroll
        for (int k = 0; k < KS; k++) {
            float w   = g1[k];
            float2 v  = sv[j][tid + k];
            float2 q  = sq[j][tid + k];
            float  p  = sp[j][tid + k];
            a0 = fmaf(w, v.x, a0);
            a1 = fmaf(w, v.y, a1);
            a2 = fmaf(w, q.x, a2);
            a3 = fmaf(w, q.y, a3);
            a4 = fmaf(w, p,   a4);
        }
        size_t o = ibase + (size_t)(r0 + j) * IMW + tid;
        d_f01[o] = __floats2half2_rn(a0, a1);
        d_f23[o] = __floats2half2_rn(a2, a3);
        d_f4[o]  = __float2half_rn(a4);
    }

    // block reduce mse -> one double atomic
    #pragma unroll
    for (int off = 16; off; off >>= 1)
        mse_loc += __shfl_down_sync(0xffffffffu, mse_loc, off);
    int lane = tid & 31, warp = tid >> 5;
    if (lane == 0) sred[warp] = (double)mse_loc;
    __syncthreads();
    if (tid == 0) {
        double m = 0.0;
        #pragma unroll
        for (int w = 0; w < 8; w++) m += sred[w];
        atomicAdd(&d_mse_sum[b], m);
    }
}

// ---------------------------------------------------------------------------
// Kernel 2 (K_V): vertical 11-tap pass + SSIM formula + reduction.
// block = 256 threads = 32 cols x 8 row-groups; each group -> 8 output rows.
// grid = (IMW/32, IMH/64, NIMG). Registers only, fp16 field loads.
// ---------------------------------------------------------------------------
__global__ __launch_bounds__(256) void bsm_v_kernel(const float* __restrict__ win)
{
    const int tid = threadIdx.x;
    const int img = blockIdx.z;
    const int b   = img / CH;

    __shared__ float g1[16];
    __shared__ double sred[8];

    if (tid < KS) {
        float s = 0.f;
        #pragma unroll
        for (int j = 0; j < KS; j++) s += win[tid * KS + j];
        g1[tid] = s;
    }
    __syncthreads();

    const int c   = tid & 31;
    const int col = blockIdx.x * 32 + c;
    const int r0  = blockIdx.y * 64 + (tid >> 5) * 8;
    const size_t ibase = (size_t)img * (IMH * IMW);

    float mu1[8], mu2[8], m11[8], m22[8], m12[8];

    // fields 0,1 (mu1, mu2)
    {
        float2 v[18];
        #pragma unroll
        for (int t = 0; t < 18; t++) {
            int rr = r0 + t - RAD;
            v[t] = (rr >= 0 && rr < IMH)
                 ? __half22float2(d_f01[ibase + (size_t)rr * IMW + col])
                 : make_float2(0.f, 0.f);
        }
        #pragma unroll
        for (int j = 0; j < 8; j++) { mu1[j] = 0.f; mu2[j] = 0.f; }
        #pragma unroll
        for (int k = 0; k < KS; k++) {
            float w = g1[k];
            #pragma unroll
            for (int j = 0; j < 8; j++) {
                mu1[j] = fmaf(w, v[j + k].x, mu1[j]);
                mu2[j] = fmaf(w, v[j + k].y, mu2[j]);
            }
        }
    }
    // fields 2,3 (m11, m22)
    {
        float2 v[18];
        #pragma unroll
        for (int t = 0; t < 18; t++) {
            int rr = r0 + t - RAD;
            v[t] = (rr >= 0 && rr < IMH)
                 ? __half22float2(d_f23[ibase + (size_t)rr * IMW + col])
                 : make_float2(0.f, 0.f);
        }
        #pragma unroll
        for (int j = 0; j < 8; j++) { m11[j] = 0.f; m22[j] = 0.f; }
        #pragma unroll
        for (int k = 0; k < KS; k++) {
            float w = g1[k];
            #pragma unroll
            for (int j = 0; j < 8; j++) {
                m11[j] = fmaf(w, v[j + k].x, m11[j]);
                m22[j] = fmaf(w, v[j + k].y, m22[j]);
            }
        }
    }
    // field 4 (m12)
    {
        float v[18];
        #pragma unroll
        for (int t = 0; t < 18; t++) {
            int rr = r0 + t - RAD;
            v[t] = (rr >= 0 && rr < IMH)
                 ? __half2float(d_f4[ibase + (size_t)rr * IMW + col]) : 0.f;
        }
        #pragma unroll
        for (int j = 0; j < 8; j++) m12[j] = 0.f;
        #pragma unroll
        for (int k = 0; k < KS; k++) {
            float w = g1[k];
            #pragma unroll
            for (int j = 0; j < 8; j++)
                m12[j] = fmaf(w, v[j + k], m12[j]);
        }
    }

    const float C1c = 0.01f * 0.01f;
    const float C2c = 0.03f * 0.03f;
    float ssim_loc = 0.f;
    #pragma unroll
    for (int j = 0; j < 8; j++) {
        float mu1s = mu1[j] * mu1[j];
        float mu2s = mu2[j] * mu2[j];
        float mu12 = mu1[j] * mu2[j];
        float s1  = m11[j] - mu1s;
        float s2  = m22[j] - mu2s;
        float s12 = m12[j] - mu12;
        float num = (2.f * mu12 + C1c) * (2.f * s12 + C2c);
        float den = (mu1s + mu2s + C1c) * (s1 + s2 + C2c);
        ssim_loc += num / den;
    }

    #pragma unroll
    for (int off = 16; off; off >>= 1)
        ssim_loc += __shfl_down_sync(0xffffffffu, ssim_loc, off);
    int lane = tid & 31, warp = tid >> 5;
    if (lane == 0) sred[warp] = (double)ssim_loc;
    __syncthreads();
    if (tid == 0) {
        double s = 0.0;
        #pragma unroll
        for (int w = 0; w < 8; w++) s += sred[w];
        atomicAdd(&d_ssim_sum[b], s);
    }
}

// ---------------------------------------------------------------------------
// Kernel 3a: histogram scan — coalesced uint4 reads, self-cleaning (writes
// zeros back so the next launch starts from a zeroed histogram).
// grid = (8 chunks, 64 batches), block = 256 (8 warps, warp -> 4 rows).
// ---------------------------------------------------------------------------
__global__ __launch_bounds__(256) void bsm_fin_a_kernel()
{
    const int b     = blockIdx.y;
    const int chunk = blockIdx.x;
    const int tid   = threadIdx.x;
    const int lane  = tid & 31;
    const int warp  = tid >> 5;

    __shared__ unsigned int spy[NB];
    __shared__ double sredA[8], sredB[8];

    spy[tid] = 0u;
    __syncthreads();

    uint4* hb4 = (uint4*)&d_hist[b * NB * NB];
    const float invNf = 1.0f / (float)NPIX;
    const uint4 z4 = make_uint4(0u, 0u, 0u, 0u);

    double hxy_loc = 0.0;
    double hx_loc  = 0.0;

    // warp handles 4 consecutive rows
    #pragma unroll
    for (int rr = 0; rr < 4; rr++) {
        int row = chunk * 32 + warp * 4 + rr;
        uint4 q0 = hb4[row * 64 + lane];
        uint4 q1 = hb4[row * 64 + 32 + lane];
        hb4[row * 64 + lane] = z4;          // self-clean for next launch
        hb4[row * 64 + 32 + lane] = z4;
        unsigned int cs[8] = {q0.x, q0.y, q0.z, q0.w, q1.x, q1.y, q1.z, q1.w};

        unsigned int px_part = 0;
        float h_part = 0.f;      // Σ -p*log2(p) over this lane's 8 bins
        #pragma unroll
        for (int k = 0; k < 8; k++) {
            unsigned int cnt = cs[k];
            px_part += cnt;
            if (cnt) {
                float p = (float)cnt * invNf;
                h_part -= p * __log2f(p);
                int colk = (k < 4) ? (lane * 4 + k) : (128 + lane * 4 + (k - 4));
                atomicAdd(&spy[colk], cnt);
            }
        }
        hxy_loc += (double)h_part;

        #pragma unroll
        for (int off = 16; off; off >>= 1)
            px_part += __shfl_down_sync(0xffffffffu, px_part, off);
        if (lane == 0 && px_part) {
            float pxn = (float)px_part * invNf;
            hx_loc -= (double)(pxn * __log2f(pxn));
        }
    }

    #pragma unroll
    for (int off = 16; off; off >>= 1)
        hxy_loc += __shfl_down_sync(0xffffffffu, hxy_loc, off);
    if (lane == 0) { sredA[warp] = hxy_loc; sredB[warp] = hx_loc; }
    __syncthreads();
    if (tid == 0) {
        double a = 0.0, bb = 0.0;
        #pragma unroll
        for (int w = 0; w < 8; w++) { a += sredA[w]; bb += sredB[w]; }
        atomicAdd(&d_hxy[b], a);
        atomicAdd(&d_hx[b],  bb);
    }
    __syncthreads();
    if (spy[tid]) atomicAdd(&d_py[b * NB + tid], spy[tid]);
}

// ---------------------------------------------------------------------------
// Kernel 3b: combine — H(Y) from d_py, final MI/SSIM/PSNR, write out.
// Self-cleaning: zeroes all per-batch accumulators after use.
// ---------------------------------------------------------------------------
__global__ __launch_bounds__(256) void bsm_fin_b_kernel(float* __restrict__ out)
{
    const int b = blockIdx.x;
    const int t = threadIdx.x;
    const float invNf = 1.0f / (float)NPIX;
    const double invN = 1.0 / (double)NPIX;

    __shared__ double shy[256];
    unsigned int py = d_py[b * NB + t];
    d_py[b * NB + t] = 0u;                   // self-clean
    float pyn = (float)py * invNf;
    shy[t] = (py > 0) ? (double)(-pyn * __log2f(pyn)) : 0.0;
    __syncthreads();
    for (int s = 128; s; s >>= 1) {
        if (t < s) shy[t] += shy[t + s];
        __syncthreads();
    }

    if (t == 0) {
        double hx = d_hx[b], hy = shy[0], hxyv = d_hxy[b];
        double ssim_s = d_ssim_sum[b];
        double mse_s  = d_mse_sum[b];
        d_hx[b] = 0.0; d_hxy[b] = 0.0;       // self-clean
        d_ssim_sum[b] = 0.0; d_mse_sum[b] = 0.0;

        double mi = hx + hy - hxyv;
        double norm = fmin(hx, hy);
        mi = (norm > 0.0) ? (mi / norm) : 0.0;
        mi = fmin(fmax(mi, 0.0), 1.0);

        double ssim = ssim_s * invN;

        double mse = mse_s * invN;
        double psnr = (mse == 0.0) ? 100.0 : (-10.0 * log10(mse));
        psnr /= 40.0;

        out[b * 3 + 0] = (float)mi;
        out[b * 3 + 1] = (float)ssim;
        out[b * 3 + 2] = (float)psnr;
    }
}

// ---------------------------------------------------------------------------
extern "C" void kernel_launch(void* const* d_in, const int* in_sizes, int n_in,
                              void* d_out, int out_size)
{
    const float* x   = (const float*)d_in[0];
    const float* y   = (const float*)d_in[1];
    const float* win = (const float*)d_in[2];
    float* out = (float*)d_out;

    dim3 gh(IMH / 4, NIMG);
    bsm_h_kernel<<<gh, 256>>>(x, y, win);

    dim3 gv(IMW / 32, IMH / 64, NIMG);
    bsm_v_kernel<<<gv, 256>>>(win);

    dim3 gf(8, BATCH);
    bsm_fin_a_kernel<<<gf, 256>>>();
    bsm_fin_b_kernel<<<BATCH, 256>>>(out);
}

// round 8
// speedup vs baseline: 1.1299x; 1.1193x over previous
#include <cuda_runtime.h>
#include <cuda_fp16.h>
#include <math.h>

#define BATCH 64
#define CH 3
#define NIMG (BATCH*CH)     /* 192 */
#define IMH 256
#define IMW 256
#define NB 256
#define NPIX (CH*IMH*IMW)   /* 196608 per batch */
#define RAD 5
#define KS 11

// Scratch (device globals: zero-initialized at module load; every launch
// leaves them zeroed again => allocation-free AND no zeroing kernel needed)
__device__ unsigned int d_hist[BATCH * NB * NB];        // 16 MB joint histograms
__device__ unsigned int d_py[BATCH * NB];               // marginal-y partial sums
__device__ double d_hx[BATCH];
__device__ double d_hxy[BATCH];
__device__ double d_ssim_sum[BATCH];
__device__ double d_mse_sum[BATCH];
// fp16-staged horizontally-convolved fields (125 MB total)
__device__ __half2 d_f01[NIMG * IMH * IMW];             // (conv x, conv y)
__device__ __half2 d_f23[NIMG * IMH * IMW];             // (conv x2, conv y2)
__device__ __half  d_f4 [NIMG * IMH * IMW];             // conv xy

// ---------------------------------------------------------------------------
// Kernel 1 (K_H): horizontal 11-tap pass over full rows + MI hist + MSE.
// block = 256 threads handles 4 rows of one image. grid = (IMH/4, NIMG).
// (round-5 body: scalar rx/ry, products computed in-loop)
// ---------------------------------------------------------------------------
__global__ __launch_bounds__(256) void bsm_h_kernel(
    const float* __restrict__ x,
    const float* __restrict__ y,
    const float* __restrict__ win)
{
    const int tid = threadIdx.x;
    const int img = blockIdx.y;
    const int b   = img / CH;
    const int r0  = blockIdx.x * 4;

    __shared__ float rx[4][268];
    __shared__ float ry[4][268];
    __shared__ float g1[16];
    __shared__ double sred[8];

    // Separable 1D gaussian = row sums of the 2D window (sum(g)=1).
    if (tid < KS) {
        float s = 0.f;
        #pragma unroll
        for (int j = 0; j < KS; j++) s += win[tid * KS + j];
        g1[tid] = s;
    }
    // zero halos (image edge -> zero pad)
    if (tid < 5) {
        #pragma unroll
        for (int j = 0; j < 4; j++) {
            rx[j][tid] = 0.f; ry[j][tid] = 0.f;
            rx[j][IMW + 5 + tid] = 0.f; ry[j][IMW + 5 + tid] = 0.f;
        }
    }

    const size_t ibase = (size_t)img * (IMH * IMW);
    float mse_loc = 0.f;

    #pragma unroll
    for (int j = 0; j < 4; j++) {
        size_t base = ibase + (size_t)(r0 + j) * IMW;
        float xv = x[base + tid];
        float yv = y[base + tid];
        rx[j][5 + tid] = xv;
        ry[j][5 + tid] = yv;

        // MI binning (exact reference op order) + MSE
        float xf = (xv + 1.0f) * 0.5f;
        float yf = (yv + 1.0f) * 0.5f;
        int ix = (int)(xf * 256.0f); ix = min(max(ix, 0), NB - 1);
        int iy = (int)(yf * 256.0f); iy = min(max(iy, 0), NB - 1);
        atomicAdd(&d_hist[b * (NB * NB) + ix * NB + iy], 1u);
        float d = (xv * 0.5f + 0.5f) - (yv * 0.5f + 0.5f);
        mse_loc = fmaf(d, d, mse_loc);
    }
    __syncthreads();

    #pragma unroll
    for (int j = 0; j < 4; j++) {
        float a0 = 0.f, a1 = 0.f, a2 = 0.f, a3 = 0.f, a4 = 0.f;
        #pragma unroll
        for (int k = 0; k < KS; k++) {
            float w  = g1[k];
            float xs = rx[j][tid + k];
            float ys = ry[j][tid + k];
            a0 = fmaf(w, xs, a0);
            a1 = fmaf(w, ys, a1);
            a2 = fmaf(w, xs * xs, a2);
            a3 = fmaf(w, ys * ys, a3);
            a4 = fmaf(w, xs * ys, a4);
        }
        size_t o = ibase + (size_t)(r0 + j) * IMW + tid;
        d_f01[o] = __floats2half2_rn(a0, a1);
        d_f23[o] = __floats2half2_rn(a2, a3);
        d_f4[o]  = __float2half_rn(a4);
    }

    // block reduce mse -> one double atomic
    #pragma unroll
    for (int off = 16; off; off >>= 1)
        mse_loc += __shfl_down_sync(0xffffffffu, mse_loc, off);
    int lane = tid & 31, warp = tid >> 5;
    if (lane == 0) sred[warp] = (double)mse_loc;
    __syncthreads();
    if (tid == 0) {
        double m = 0.0;
        #pragma unroll
        for (int w = 0; w < 8; w++) m += sred[w];
        atomicAdd(&d_mse_sum[b], m);
    }
}

// ---------------------------------------------------------------------------
// Kernel 2 (K_V): vertical 11-tap pass + SSIM formula + reduction.
// block = 256 threads = 32 cols x 8 row-groups; each row-group -> 4 rows.
// grid = (IMW/32, IMH/32, NIMG). Registers only, fp16 field loads.
// (round-5 body: 4 rows/thread)
// ---------------------------------------------------------------------------
__global__ __launch_bounds__(256) void bsm_v_kernel(const float* __restrict__ win)
{
    const int tid = threadIdx.x;
    const int img = blockIdx.z;
    const int b   = img / CH;

    __shared__ float g1[16];
    __shared__ double sred[8];

    if (tid < KS) {
        float s = 0.f;
        #pragma unroll
        for (int j = 0; j < KS; j++) s += win[tid * KS + j];
        g1[tid] = s;
    }
    __syncthreads();

    const int c   = tid & 31;
    const int col = blockIdx.x * 32 + c;
    const int r0  = blockIdx.y * 32 + (tid >> 5) * 4;
    const size_t ibase = (size_t)img * (IMH * IMW);

    float mu1[4], mu2[4], m11[4], m22[4], m12[4];

    // fields 0,1 (mu1, mu2)
    {
        float2 v[14];
        #pragma unroll
        for (int t = 0; t < 14; t++) {
            int rr = r0 + t - RAD;
            v[t] = (rr >= 0 && rr < IMH)
                 ? __half22float2(d_f01[ibase + (size_t)rr * IMW + col])
                 : make_float2(0.f, 0.f);
        }
        #pragma unroll
        for (int j = 0; j < 4; j++) { mu1[j] = 0.f; mu2[j] = 0.f; }
        #pragma unroll
        for (int k = 0; k < KS; k++) {
            float w = g1[k];
            #pragma unroll
            for (int j = 0; j < 4; j++) {
                mu1[j] = fmaf(w, v[j + k].x, mu1[j]);
                mu2[j] = fmaf(w, v[j + k].y, mu2[j]);
            }
        }
    }
    // fields 2,3 (m11, m22)
    {
        float2 v[14];
        #pragma unroll
        for (int t = 0; t < 14; t++) {
            int rr = r0 + t - RAD;
            v[t] = (rr >= 0 && rr < IMH)
                 ? __half22float2(d_f23[ibase + (size_t)rr * IMW + col])
                 : make_float2(0.f, 0.f);
        }
        #pragma unroll
        for (int j = 0; j < 4; j++) { m11[j] = 0.f; m22[j] = 0.f; }
        #pragma unroll
        for (int k = 0; k < KS; k++) {
            float w = g1[k];
            #pragma unroll
            for (int j = 0; j < 4; j++) {
                m11[j] = fmaf(w, v[j + k].x, m11[j]);
                m22[j] = fmaf(w, v[j + k].y, m22[j]);
            }
        }
    }
    // field 4 (m12)
    {
        float v[14];
        #pragma unroll
        for (int t = 0; t < 14; t++) {
            int rr = r0 + t - RAD;
            v[t] = (rr >= 0 && rr < IMH)
                 ? __half2float(d_f4[ibase + (size_t)rr * IMW + col]) : 0.f;
        }
        #pragma unroll
        for (int j = 0; j < 4; j++) m12[j] = 0.f;
        #pragma unroll
        for (int k = 0; k < KS; k++) {
            float w = g1[k];
            #pragma unroll
            for (int j = 0; j < 4; j++)
                m12[j] = fmaf(w, v[j + k], m12[j]);
        }
    }

    const float C1c = 0.01f * 0.01f;
    const float C2c = 0.03f * 0.03f;
    float ssim_loc = 0.f;
    #pragma unroll
    for (int j = 0; j < 4; j++) {
        float mu1s = mu1[j] * mu1[j];
        float mu2s = mu2[j] * mu2[j];
        float mu12 = mu1[j] * mu2[j];
        float s1  = m11[j] - mu1s;
        float s2  = m22[j] - mu2s;
        float s12 = m12[j] - mu12;
        float num = (2.f * mu12 + C1c) * (2.f * s12 + C2c);
        float den = (mu1s + mu2s + C1c) * (s1 + s2 + C2c);
        ssim_loc += num / den;
    }

    #pragma unroll
    for (int off = 16; off; off >>= 1)
        ssim_loc += __shfl_down_sync(0xffffffffu, ssim_loc, off);
    int lane = tid & 31, warp = tid >> 5;
    if (lane == 0) sred[warp] = (double)ssim_loc;
    __syncthreads();
    if (tid == 0) {
        double s = 0.0;
        #pragma unroll
        for (int w = 0; w < 8; w++) s += sred[w];
        atomicAdd(&d_ssim_sum[b], s);
    }
}

// ---------------------------------------------------------------------------
// Kernel 3a: histogram scan — coalesced uint4 reads, self-cleaning (writes
// zeros back so the next launch starts from a zeroed histogram).
// grid = (8 chunks, 64 batches), block = 256 (8 warps, warp -> 4 rows).
// ---------------------------------------------------------------------------
__global__ __launch_bounds__(256) void bsm_fin_a_kernel()
{
    const int b     = blockIdx.y;
    const int chunk = blockIdx.x;
    const int tid   = threadIdx.x;
    const int lane  = tid & 31;
    const int warp  = tid >> 5;

    __shared__ unsigned int spy[NB];
    __shared__ double sredA[8], sredB[8];

    spy[tid] = 0u;
    __syncthreads();

    uint4* hb4 = (uint4*)&d_hist[b * NB * NB];
    const float invNf = 1.0f / (float)NPIX;
    const uint4 z4 = make_uint4(0u, 0u, 0u, 0u);

    double hxy_loc = 0.0;
    double hx_loc  = 0.0;

    // warp handles 4 consecutive rows
    #pragma unroll
    for (int rr = 0; rr < 4; rr++) {
        int row = chunk * 32 + warp * 4 + rr;
        uint4 q0 = hb4[row * 64 + lane];
        uint4 q1 = hb4[row * 64 + 32 + lane];
        hb4[row * 64 + lane] = z4;          // self-clean for next launch
        hb4[row * 64 + 32 + lane] = z4;
        unsigned int cs[8] = {q0.x, q0.y, q0.z, q0.w, q1.x, q1.y, q1.z, q1.w};

        unsigned int px_part = 0;
        float h_part = 0.f;      // Σ -p*log2(p) over this lane's 8 bins
        #pragma unroll
        for (int k = 0; k < 8; k++) {
            unsigned int cnt = cs[k];
            px_part += cnt;
            if (cnt) {
                float p = (float)cnt * invNf;
                h_part -= p * __log2f(p);
                int colk = (k < 4) ? (lane * 4 + k) : (128 + lane * 4 + (k - 4));
                atomicAdd(&spy[colk], cnt);
            }
        }
        hxy_loc += (double)h_part;

        #pragma unroll
        for (int off = 16; off; off >>= 1)
            px_part += __shfl_down_sync(0xffffffffu, px_part, off);
        if (lane == 0 && px_part) {
            float pxn = (float)px_part * invNf;
            hx_loc -= (double)(pxn * __log2f(pxn));
        }
    }

    #pragma unroll
    for (int off = 16; off; off >>= 1)
        hxy_loc += __shfl_down_sync(0xffffffffu, hxy_loc, off);
    if (lane == 0) { sredA[warp] = hxy_loc; sredB[warp] = hx_loc; }
    __syncthreads();
    if (tid == 0) {
        double a = 0.0, bb = 0.0;
        #pragma unroll
        for (int w = 0; w < 8; w++) { a += sredA[w]; bb += sredB[w]; }
        atomicAdd(&d_hxy[b], a);
        atomicAdd(&d_hx[b],  bb);
    }
    __syncthreads();
    if (spy[tid]) atomicAdd(&d_py[b * NB + tid], spy[tid]);
}

// ---------------------------------------------------------------------------
// Kernel 3b: combine — H(Y) from d_py, final MI/SSIM/PSNR, write out.
// Self-cleaning: zeroes all per-batch accumulators after use.
// ---------------------------------------------------------------------------
__global__ __launch_bounds__(256) void bsm_fin_b_kernel(float* __restrict__ out)
{
    const int b = blockIdx.x;
    const int t = threadIdx.x;
    const float invNf = 1.0f / (float)NPIX;
    const double invN = 1.0 / (double)NPIX;

    __shared__ double shy[256];
    unsigned int py = d_py[b * NB + t];
    d_py[b * NB + t] = 0u;                   // self-clean
    float pyn = (float)py * invNf;
    shy[t] = (py > 0) ? (double)(-pyn * __log2f(pyn)) : 0.0;
    __syncthreads();
    for (int s = 128; s; s >>= 1) {
        if (t < s) shy[t] += shy[t + s];
        __syncthreads();
    }

    if (t == 0) {
        double hx = d_hx[b], hy = shy[0], hxyv = d_hxy[b];
        double ssim_s = d_ssim_sum[b];
        double mse_s  = d_mse_sum[b];
        d_hx[b] = 0.0; d_hxy[b] = 0.0;       // self-clean
        d_ssim_sum[b] = 0.0; d_mse_sum[b] = 0.0;

        double mi = hx + hy - hxyv;
        double norm = fmin(hx, hy);
        mi = (norm > 0.0) ? (mi / norm) : 0.0;
        mi = fmin(fmax(mi, 0.0), 1.0);

        double ssim = ssim_s * invN;

        double mse = mse_s * invN;
        double psnr = (mse == 0.0) ? 100.0 : (-10.0 * log10(mse));
        psnr /= 40.0;

        out[b * 3 + 0] = (float)mi;
        out[b * 3 + 1] = (float)ssim;
        out[b * 3 + 2] = (float)psnr;
    }
}

// ---------------------------------------------------------------------------
extern "C" void kernel_launch(void* const* d_in, const int* in_sizes, int n_in,
                              void* d_out, int out_size)
{
    const float* x   = (const float*)d_in[0];
    const float* y   = (const float*)d_in[1];
    const float* win = (const float*)d_in[2];
    float* out = (float*)d_out;

    dim3 gh(IMH / 4, NIMG);
    bsm_h_kernel<<<gh, 256>>>(x, y, win);

    dim3 gv(IMW / 32, IMH / 32, NIMG);
    bsm_v_kernel<<<gv, 256>>>(win);

    dim3 gf(8, BATCH);
    bsm_fin_a_kernel<<<gf, 256>>>();
    bsm_fin_b_kernel<<<BATCH, 256>>>(out);
}